// round 10
// baseline (speedup 1.0000x reference)
#include <cuda_runtime.h>

#define HW (512 * 512)
#define EPS 1e-6f

__global__ __launch_bounds__(128) void Interpolate_28664611734214_kernel(
    const float4* __restrict__ data4,    // (9,9,512,512,3) viewed as float4 chunks
    const float*  __restrict__ cam_xyz,  // (3,)
    const int*    __restrict__ neighbors,// (4,2)
    const int2*   __restrict__ uv,       // (4,512,512,2) as int2
    float*        __restrict__ out)      // flat (HW,3) == reshape(3,H,W)
{
    const int pix = blockIdx.x * blockDim.x + threadIdx.x;   // grid tiles HW exactly

    // ---- head of the critical path: issue all 4 uv loads first ----
    int2 q[4];
#pragma unroll
    for (int n = 0; n < 4; n++)
        q[n] = __ldg(uv + n * HW + pix);

    // ---- weights (tiny; all loads L1-broadcast; fills the uv-load shadow) ----
    const float c0 = __ldg(cam_xyz + 0);
    const float c1 = __ldg(cam_xyz + 1);

    int n0[4], n1[4];
    float t[4];
#pragma unroll
    for (int j = 0; j < 4; j++) {
        n0[j] = __ldg(neighbors + 2 * j + 0);
        n1[j] = __ldg(neighbors + 2 * j + 1);
        const float d0 = c0 - (float)n0[j];
        const float d1 = c1 - (float)n1[j];
        float v = fabsf(d0 * d1);
        t[j] = (v <= EPS) ? 0.0f : v;   // threshold BEFORE sum (matches ref)
    }
    const float s = t[0] + t[1] + t[2] + t[3];

    float w[4];
#pragma unroll
    for (int n = 0; n < 4; n++) {
        // flip: weight for gathered[n] pairs with t of neighbor (3-n)
        const float x = t[3 - n] / s;
        w[n] = (fabsf(x) <= EPS) ? 0.0f : x;
    }

    // ---- gather + weighted sum: L1-BYPASS (.cg) divergent loads ----
    float r = 0.f, g = 0.f, b = 0.f;
#pragma unroll
    for (int n = 0; n < 4; n++) {
        // float index of R channel: f = 3 * point_idx  (< 64M, fits int32)
        const int f     = (((n0[n] * 9 + n1[n]) * 512 + q[n].x) * 512 + q[n].y) * 3;
        const int chunk = f >> 2;       // float4 index
        const int o     = f & 3;        // offset within chunk

        const float4 A = __ldcg(data4 + chunk);          // L2-only, no L1 fill
        float2 B = make_float2(0.f, 0.f);
        if (o >= 2)                      // predicated; ~half the lanes
            B = __ldcg((const float2*)(data4 + chunk + 1));

        float rr, gg, bb;
        if (o == 0)      { rr = A.x; gg = A.y; bb = A.z; }
        else if (o == 1) { rr = A.y; gg = A.z; bb = A.w; }
        else if (o == 2) { rr = A.z; gg = A.w; bb = B.x; }
        else             { rr = A.w; gg = B.x; bb = B.y; }

        const float wn = w[n];
        r += wn * rr;
        g += wn * gg;
        b += wn * bb;
    }

    // einsum result is (HW,3) then reinterpreted as (3,H,W): interleaved layout
    out[3 * pix + 0] = r;
    out[3 * pix + 1] = g;
    out[3 * pix + 2] = b;
}

extern "C" void kernel_launch(void* const* d_in, const int* in_sizes, int n_in,
                              void* d_out, int out_size) {
    // metadata order: data, pixel, cam_xyz, neighbors, uv
    const float4* data4     = (const float4*)d_in[0];
    // d_in[1] = pixel, only its shape is used by the reference -> unused here
    const float*  cam_xyz   = (const float*)d_in[2];
    const int*    neighbors = (const int*)d_in[3];
    const int2*   uv        = (const int2*)d_in[4];
    float*        out       = (float*)d_out;

    const int threads = 128;
    const int blocks  = HW / threads;   // 2048, tiles HW exactly
    Interpolate_28664611734214_kernel<<<blocks, threads>>>(
        data4, cam_xyz, neighbors, uv, out);
}

// round 11
// speedup vs baseline: 1.1483x; 1.1483x over previous
#include <cuda_runtime.h>

#define HW (512 * 512)
#define EPS 1e-6f

__global__ __launch_bounds__(256) void Interpolate_28664611734214_kernel(
    const float4* __restrict__ data4,    // (9,9,512,512,3) viewed as float4 chunks
    const float*  __restrict__ cam_xyz,  // (3,)
    const int*    __restrict__ neighbors,// (4,2)
    const int2*   __restrict__ uv,       // (4,512,512,2) as int2
    float*        __restrict__ out)      // flat (HW,3) == reshape(3,H,W)
{
    const int pix = blockIdx.x * blockDim.x + threadIdx.x;   // grid tiles HW exactly

    // ---- head of the critical path: issue all 4 uv loads first ----
    int2 q[4];
#pragma unroll
    for (int n = 0; n < 4; n++)
        q[n] = __ldg(uv + n * HW + pix);

    // ---- weights (tiny; all loads L1-broadcast; fills the uv-load shadow) ----
    const float c0 = __ldg(cam_xyz + 0);
    const float c1 = __ldg(cam_xyz + 1);

    int n0[4], n1[4];
    float t[4];
#pragma unroll
    for (int j = 0; j < 4; j++) {
        n0[j] = __ldg(neighbors + 2 * j + 0);
        n1[j] = __ldg(neighbors + 2 * j + 1);
        const float d0 = c0 - (float)n0[j];
        const float d1 = c1 - (float)n1[j];
        float v = fabsf(d0 * d1);
        t[j] = (v <= EPS) ? 0.0f : v;   // threshold BEFORE sum (matches ref)
    }
    const float s = t[0] + t[1] + t[2] + t[3];

    float w[4];
#pragma unroll
    for (int n = 0; n < 4; n++) {
        // flip: weight for gathered[n] pairs with t of neighbor (3-n)
        const float x = t[3 - n] / s;
        w[n] = (fabsf(x) <= EPS) ? 0.0f : x;
    }

    // ---- gather + weighted sum (L1-allocating .nc loads; compiler-scheduled) ----
    float r = 0.f, g = 0.f, b = 0.f;
#pragma unroll
    for (int n = 0; n < 4; n++) {
        // float index of R channel: f = 3 * point_idx  (< 64M, fits int32)
        const int f     = (((n0[n] * 9 + n1[n]) * 512 + q[n].x) * 512 + q[n].y) * 3;
        const int chunk = f >> 2;       // float4 index
        const int o     = f & 3;        // offset within chunk

        const float4 A = __ldg(data4 + chunk);           // 1 line miss (~2.5 cyc/wf)
        float2 B = make_float2(0.f, 0.f);
        if (o >= 2)                      // predicated; ~half lanes; mostly L1 hits
            B = __ldg((const float2*)(data4 + chunk + 1));

        float rr, gg, bb;
        if (o == 0)      { rr = A.x; gg = A.y; bb = A.z; }
        else if (o == 1) { rr = A.y; gg = A.z; bb = A.w; }
        else if (o == 2) { rr = A.z; gg = A.w; bb = B.x; }
        else             { rr = A.w; gg = B.x; bb = B.y; }

        const float wn = w[n];
        r += wn * rr;
        g += wn * gg;
        b += wn * bb;
    }

    // einsum result is (HW,3) then reinterpreted as (3,H,W): interleaved layout
    out[3 * pix + 0] = r;
    out[3 * pix + 1] = g;
    out[3 * pix + 2] = b;
}

extern "C" void kernel_launch(void* const* d_in, const int* in_sizes, int n_in,
                              void* d_out, int out_size) {
    // metadata order: data, pixel, cam_xyz, neighbors, uv
    const float4* data4     = (const float4*)d_in[0];
    // d_in[1] = pixel, only its shape is used by the reference -> unused here
    const float*  cam_xyz   = (const float*)d_in[2];
    const int*    neighbors = (const int*)d_in[3];
    const int2*   uv        = (const int2*)d_in[4];
    float*        out       = (float*)d_out;

    const int threads = 256;
    const int blocks  = HW / threads;   // 1024, tiles HW exactly
    Interpolate_28664611734214_kernel<<<blocks, threads>>>(
        data4, cam_xyz, neighbors, uv, out);
}